// round 9
// baseline (speedup 1.0000x reference)
#include <cuda_runtime.h>
#include <cstdint>

#define NN 100000
#define NE 1600000
#define DIM 128
#define SLOTS 128

typedef unsigned long long u64;

// ---------------------------------------------------------------------------
// Scratch (__device__ globals)
// ---------------------------------------------------------------------------
__device__ float g_mean[NN * DIM];
__device__ float g_h1[NN * DIM];
__device__ float g_h2[NN * DIM];
__device__ int   g_cursor[NN];
__device__ int   g_csrsrc[NN * SLOTS];

// ---------------------------------------------------------------------------
// f32x2 helpers (Blackwell packed fp32 FMA)
// ---------------------------------------------------------------------------
__device__ __forceinline__ u64 dup2(float v) {
    u64 r; asm("mov.b64 %0, {%1, %1};" : "=l"(r) : "f"(v)); return r;
}
__device__ __forceinline__ float2 unpack2(u64 v) {
    float2 p; asm("mov.b64 {%0, %1}, %2;" : "=f"(p.x), "=f"(p.y) : "l"(v)); return p;
}
__device__ __forceinline__ void ffma2(u64& d, u64 a, u64 b) {
    asm("fma.rn.f32x2 %0, %1, %2, %0;" : "+l"(d) : "l"(a), "l"(b));
}

// ---------------------------------------------------------------------------
// padded-bucket CSR build
// ---------------------------------------------------------------------------
__global__ void k_init_cursor() {
    int i = blockIdx.x * blockDim.x + threadIdx.x;
    if (i < NN) g_cursor[i] = i * SLOTS;
}

__global__ void k_bucket(const int* __restrict__ src, const int* __restrict__ dst) {
    int e = blockIdx.x * blockDim.x + threadIdx.x;
    if (e < NE) {
        int d = dst[e];
        int pos = atomicAdd(&g_cursor[d], 1);
        if (pos < d * SLOTS + SLOTS)
            g_csrsrc[pos] = src[e];
    }
}

// ---------------------------------------------------------------------------
// pull-mode mean aggregation: one warp per node, lane owns one float4.
// ---------------------------------------------------------------------------
__global__ void __launch_bounds__(256)
k_agg(const float* __restrict__ x, float* __restrict__ mean) {
    int node = (blockIdx.x * blockDim.x + threadIdx.x) >> 5;
    int lane = threadIdx.x & 31;
    if (node >= NN) return;
    int beg = node * SLOTS;
    int d   = min(__ldg(g_cursor + node) - beg, SLOTS);
    int end = beg + d;

    const float4* xv = (const float4*)x;
    float4 acc = make_float4(0.f, 0.f, 0.f, 0.f);
    for (int e = beg; e < end; e += 8) {
        int idx[8];
#pragma unroll
        for (int j = 0; j < 8; ++j)
            idx[j] = (e + j < end) ? __ldg(g_csrsrc + e + j) : -1;
#pragma unroll
        for (int j = 0; j < 8; ++j) {
            if (idx[j] >= 0) {
                float4 v = __ldg(xv + (size_t)idx[j] * 32 + lane);
                acc.x += v.x; acc.y += v.y; acc.z += v.z; acc.w += v.w;
            }
        }
    }
    float inv = (d > 0) ? (1.0f / (float)d) : 0.0f;
    acc.x *= inv; acc.y *= inv; acc.z *= inv; acc.w *= inv;
    ((float4*)(mean + (size_t)node * DIM))[lane] = acc;
}

// ---------------------------------------------------------------------------
// fused SAGE GEMM, all operands in SMEM:
//   out[n,:] = act( mean[n,:] @ Wl + hin[n,:] @ Wr + b )
//
// 256 threads = (tx 0..15: 8 cols) x (ty 0..15: rows {ty, ty+16, ty+32, ty+48}),
// tile 64 rows x 128 cols, acc 4x4 u64/thread (32 regs).
// Per phase: stage input tile (33.8KB) + weight matrix (64KB) into SMEM, then
// the k-loop reads ONLY smem (LDS.128 both operands; 29cyc fixed, no L1
// misses — R7's binder was weight-LDG L1 thrash at L1D=92KB < 128KB WS).
// 99KB smem/block -> 2 blocks/SM = 16 warps; FMA pipe becomes the binder.
// ---------------------------------------------------------------------------
template <bool RELU>
__global__ void __launch_bounds__(256, 2)
k_gemm(const float* __restrict__ mean,
       const float* __restrict__ hin,
       const float* __restrict__ Wl,
       const float* __restrict__ Wr,
       const float* __restrict__ bias,
       float* __restrict__ out) {
    constexpr int ROWS = 64;
    constexpr int STR  = DIM + 4;   // 132 floats, rows 16B-aligned
    extern __shared__ float smem_f[];
    float* s_in = smem_f;                     // 64*132 = 8448 floats
    float* s_w  = smem_f + ROWS * STR;        // 128*128 = 16384 floats

    const int tx = threadIdx.x & 15;
    const int ty = threadIdx.x >> 4;
    const int row0 = blockIdx.x * ROWS;

    u64 acc[4][4];
#pragma unroll
    for (int i = 0; i < 4; ++i)
#pragma unroll
        for (int j = 0; j < 4; ++j) acc[i][j] = 0ull;

#pragma unroll
    for (int phase = 0; phase < 2; ++phase) {
        const float* base = phase ? hin : mean;
        const float* W    = phase ? Wr  : Wl;

        __syncthreads();
        // stage 64x128 input tile
        for (int t = threadIdx.x; t < ROWS * 32; t += 256) {
            int r  = t >> 5;
            int c4 = t & 31;
            int grow = row0 + r;
            float4 v = make_float4(0.f, 0.f, 0.f, 0.f);
            if (grow < NN)
                v = __ldg(((const float4*)(base + (size_t)grow * DIM)) + c4);
            *(float4*)(s_in + r * STR + c4 * 4) = v;
        }
        // stage 128x128 weight matrix (flat row-major)
        for (int t = threadIdx.x; t < DIM * 32; t += 256)
            *(float4*)(s_w + t * 4) = __ldg((const float4*)W + t);
        __syncthreads();

        const ulonglong2* sw2 = (const ulonglong2*)s_w;  // [k*32 + c2]
#pragma unroll 4
        for (int k0 = 0; k0 < DIM; k0 += 4) {
            float4 sv4[4];
#pragma unroll
            for (int i = 0; i < 4; ++i)
                sv4[i] = *(const float4*)(s_in + (ty + 16 * i) * STR + k0);
#pragma unroll
            for (int kk = 0; kk < 4; ++kk) {
                int k = k0 + kk;
                ulonglong2 wa = sw2[k * 32 + tx * 2];
                ulonglong2 wb = sw2[k * 32 + tx * 2 + 1];
#pragma unroll
                for (int i = 0; i < 4; ++i) {
                    float f = (kk == 0) ? sv4[i].x : (kk == 1) ? sv4[i].y
                              : (kk == 2) ? sv4[i].z : sv4[i].w;
                    u64 s = dup2(f);
                    ffma2(acc[i][0], s, wa.x);
                    ffma2(acc[i][1], s, wa.y);
                    ffma2(acc[i][2], s, wb.x);
                    ffma2(acc[i][3], s, wb.y);
                }
            }
        }
    }

    // epilogue
    float4 b0 = __ldg((const float4*)(bias + tx * 8));
    float4 b1 = __ldg((const float4*)(bias + tx * 8) + 1);

#pragma unroll
    for (int i = 0; i < 4; ++i) {
        int grow = row0 + ty + i * 16;
        if (grow >= NN) continue;
        float2 p0 = unpack2(acc[i][0]);
        float2 p1 = unpack2(acc[i][1]);
        float2 p2 = unpack2(acc[i][2]);
        float2 p3 = unpack2(acc[i][3]);
        float4 o0 = make_float4(p0.x + b0.x, p0.y + b0.y, p1.x + b0.z, p1.y + b0.w);
        float4 o1 = make_float4(p2.x + b1.x, p2.y + b1.y, p3.x + b1.z, p3.y + b1.w);
        if (RELU) {
            o0.x = fmaxf(o0.x, 0.f); o0.y = fmaxf(o0.y, 0.f);
            o0.z = fmaxf(o0.z, 0.f); o0.w = fmaxf(o0.w, 0.f);
            o1.x = fmaxf(o1.x, 0.f); o1.y = fmaxf(o1.y, 0.f);
            o1.z = fmaxf(o1.z, 0.f); o1.w = fmaxf(o1.w, 0.f);
        }
        float* op = out + (size_t)grow * DIM + tx * 8;
        *(float4*)(op)     = o0;
        *(float4*)(op + 4) = o1;
    }
}

// ---------------------------------------------------------------------------
// kernel_launch — launch index 3 = k_gemm layer 1 (ncu target)
// inputs: t, x, edge_index, W1_l, W1_r, b1, W2_l, W2_r, b2, W3_l, W3_r, b3
// ---------------------------------------------------------------------------
extern "C" void kernel_launch(void* const* d_in, const int* in_sizes, int n_in,
                              void* d_out, int out_size) {
    const float* x   = (const float*)d_in[1];
    const int*   ei  = (const int*)d_in[2];
    const int*   src = ei;
    const int*   dst = ei + NE;
    const float* W1l = (const float*)d_in[3];
    const float* W1r = (const float*)d_in[4];
    const float* b1  = (const float*)d_in[5];
    const float* W2l = (const float*)d_in[6];
    const float* W2r = (const float*)d_in[7];
    const float* b2  = (const float*)d_in[8];
    const float* W3l = (const float*)d_in[9];
    const float* W3r = (const float*)d_in[10];
    const float* b3  = (const float*)d_in[11];
    float* out = (float*)d_out;

    float *mean, *h1, *h2;
    cudaGetSymbolAddress((void**)&mean, g_mean);
    cudaGetSymbolAddress((void**)&h1,  g_h1);
    cudaGetSymbolAddress((void**)&h2,  g_h2);

    const int SMEM = (64 * (DIM + 4) + DIM * DIM) * 4;   // 99328 B
    cudaFuncSetAttribute(k_gemm<true>,  cudaFuncAttributeMaxDynamicSharedMemorySize, SMEM);
    cudaFuncSetAttribute(k_gemm<false>, cudaFuncAttributeMaxDynamicSharedMemorySize, SMEM);

    const int AGG_BLOCKS  = (NN * 32 + 255) / 256;
    const int GEMM_BLOCKS = (NN + 63) / 64;

    // padded-bucket CSR build (launches 0-1)
    k_init_cursor<<<(NN + 255) / 256, 256>>>();
    k_bucket<<<(NE + 255) / 256, 256>>>(src, dst);

    // layer 1 (launch 2 = agg, launch 3 = gemm -> ncu target)
    k_agg<<<AGG_BLOCKS, 256>>>(x, mean);
    k_gemm<true><<<GEMM_BLOCKS, 256, SMEM>>>(mean, x, W1l, W1r, b1, h1);

    // layer 2
    k_agg<<<AGG_BLOCKS, 256>>>(h1, mean);
    k_gemm<true><<<GEMM_BLOCKS, 256, SMEM>>>(mean, h1, W2l, W2r, b2, h2);

    // layer 3 (no relu)
    k_agg<<<AGG_BLOCKS, 256>>>(h2, mean);
    k_gemm<false><<<GEMM_BLOCKS, 256, SMEM>>>(mean, h2, W3l, W3r, b3, out);
}